// round 8
// baseline (speedup 1.0000x reference)
#include <cuda_runtime.h>
#include <cuda_bf16.h>
#include <cstdint>

#define Nn 100000
#define Ee 1600000
#define FIN 128
#define K1 129
#define HD 128
#define NCARDS 110
#define STR 132
#define TILE_M 128
#define NTILES ((Nn + TILE_M - 1) / TILE_M)   // 782

typedef unsigned int u32;

// ---------------- device scratch ----------------
__device__ float g_h0[(size_t)Nn * STR];   // fp32, col128 = cards
__device__ float g_h1[(size_t)Nn * STR];   // fp32 layer-1 output (gather source for layer 2)
__device__ __nv_bfloat16 g_b0h[(size_t)Nn * HD], g_b0l[(size_t)Nn * HD];
__device__ __nv_bfloat16 g_b1h[(size_t)Nn * HD], g_b1l[(size_t)Nn * HD];
__device__ __nv_bfloat16 g_b2h[(size_t)Nn * HD], g_b2l[(size_t)Nn * HD];
// bf16 split weights: 0=Wl1,1=Wr1,2=Wl2,3=Wr2,4=Wo  (padded [128,128], row-major [n][k])
__device__ __nv_bfloat16 g_Whi[5][HD * HD];
__device__ __nv_bfloat16 g_Wlo[5][HD * HD];
__device__ int g_degc[Nn];
__device__ int g_cnt[Nn];
__device__ int g_offs[Nn];
__device__ int g_csrc[Ee];
__device__ int g_tot;
__device__ int g_is64;

// ---------------- helpers ----------------
__device__ __forceinline__ unsigned load_ei(const int* p, size_t i, int is64) {
    if (is64) return (unsigned)((const long long*)p)[i];
    return (unsigned)p[i];
}
__device__ __forceinline__ uint32_t smem_u32(const void* p) {
    uint32_t a;
    asm("{ .reg .u64 t; cvta.to.shared.u64 t, %1; cvt.u32.u64 %0, t; }" : "=r"(a) : "l"(p));
    return a;
}
__device__ __forceinline__ u32 cvt2(float a, float b) {
    __nv_bfloat162 t = __floats2bfloat162_rn(a, b);
    return *(u32*)&t;
}
__device__ __forceinline__ void split2(float f0, float f1, u32& hw, u32& lw) {
    __nv_bfloat16 h0 = __float2bfloat16_rn(f0);
    __nv_bfloat16 h1 = __float2bfloat16_rn(f1);
    hw = ((u32)*(unsigned short*)&h1 << 16) | *(unsigned short*)&h0;
    lw = cvt2(f0 - __bfloat162float(h0), f1 - __bfloat162float(h1));
}

#define LDM4(r, addr) \
    asm volatile("ldmatrix.sync.aligned.m8n8.x4.shared.b16 {%0,%1,%2,%3}, [%4];" \
                 : "=r"((r)[0]), "=r"((r)[1]), "=r"((r)[2]), "=r"((r)[3]) : "r"(addr))

#define MMA(c, a, bb0, bb1) \
    asm volatile("mma.sync.aligned.m16n8k16.row.col.f32.bf16.bf16.f32 " \
                 "{%0,%1,%2,%3},{%4,%5,%6,%7},{%8,%9},{%0,%1,%2,%3};" \
                 : "+f"((c)[0]), "+f"((c)[1]), "+f"((c)[2]), "+f"((c)[3]) \
                 : "r"((a)[0]), "r"((a)[1]), "r"((a)[2]), "r"((a)[3]), "r"(bb0), "r"(bb1))

#define CPA(dst, src) \
    asm volatile("cp.async.cg.shared.global [%0], [%1], 16;" :: "r"(dst), "l"(src))
#define CPA_COMMIT() asm volatile("cp.async.commit_group;" ::: "memory")
#define CPA_WAIT()   asm volatile("cp.async.wait_group 0;" ::: "memory")

// smem; row stride 272B = 17*16 -> conflict-free ldmatrix
#define RS 272
#define S_AHI 0
#define S_ALO 34816
#define S_WHI 69632
#define S_WLO 104448
#define S_AUX 139264   // auxb[128], auxl[128], auxr[128], meanbuf[128] floats
#define SMEM_DYN (139264 + 4 * 128 * 4)

// ---------------- setup (+dtype detect) ----------------
__global__ void k_init(const int* __restrict__ ei32) {
    int i = blockIdx.x * blockDim.x + threadIdx.x;
    if (i < Nn) { g_degc[i] = 0; g_cnt[i] = 0; }
    if (i == 0) {
        g_tot = 0;
        int all_zero = 1;
        for (int w = 1; w < 64; w += 2)
            if (ei32[w] != 0) { all_zero = 0; break; }
        g_is64 = all_zero;
    }
}

__global__ void k_prep_w(const float* __restrict__ Wl1, const float* __restrict__ Wr1,
                         const float* __restrict__ Wl2, const float* __restrict__ Wr2,
                         const float* __restrict__ Wo) {
    int i = blockIdx.x * blockDim.x + threadIdx.x;
    if (i >= 5 * HD * HD) return;
    int op = i / (HD * HD);
    int r = i % (HD * HD);
    int n = r / HD, k = r % HD;
    float v = 0.f;
    if (op == 0) v = Wl1[n * K1 + k];
    else if (op == 1) v = Wr1[n * K1 + k];
    else if (op == 2) v = Wl2[n * HD + k];
    else if (op == 3) v = Wr2[n * HD + k];
    else if (n < NCARDS) v = Wo[n * HD + k];
    __nv_bfloat16 h = __float2bfloat16_rn(v);
    g_Whi[op][r] = h;
    g_Wlo[op][r] = __float2bfloat16_rn(v - __bfloat162float(h));
}

__global__ void k_concat(const float* __restrict__ x, const int* __restrict__ cards) {
    int i = blockIdx.x * blockDim.x + threadIdx.x;
    if (i >= Nn * 32) return;
    int n = i >> 5, c = (i & 31) * 4;
    float4 v = *(const float4*)(x + (size_t)n * FIN + c);
    *(float4*)(g_h0 + (size_t)n * STR + c) = v;
    uint2 hv, lv;
    split2(v.x, v.y, hv.x, lv.x);
    split2(v.z, v.w, hv.y, lv.y);
    *(uint2*)(g_b0h + (size_t)n * HD + c) = hv;
    *(uint2*)(g_b0l + (size_t)n * HD + c) = lv;
    if ((i & 31) == 0)
        *(float4*)(g_h0 + (size_t)n * STR + 128) = make_float4((float)cards[n], 0.f, 0.f, 0.f);
}

// ---------------- CSR build ----------------
__global__ void k_deghist(const int* __restrict__ ei) {
    int e = blockIdx.x * blockDim.x + threadIdx.x;
    if (e < Ee) {
        unsigned d = load_ei(ei, (size_t)Ee + e, g_is64);
        if (d < Nn) atomicAdd(&g_degc[d], 1);
    }
}

// single-kernel scan: block-local scan + atomic block base (order-free CSR layout)
__global__ void k_scanA() {
    __shared__ int sh[1024];
    __shared__ int base;
    int t = threadIdx.x;
    int n = blockIdx.x * 1024 + t;
    int v = (n < Nn) ? g_degc[n] : 0;
    sh[t] = v;
    __syncthreads();
    for (int off = 1; off < 1024; off <<= 1) {
        int add = (t >= off) ? sh[t - off] : 0;
        __syncthreads();
        sh[t] += add;
        __syncthreads();
    }
    if (t == 1023) base = atomicAdd(&g_tot, sh[1023]);
    __syncthreads();
    if (n < Nn) g_offs[n] = base + sh[t] - v;
}

__global__ void k_place(const int* __restrict__ ei) {
    int e = blockIdx.x * blockDim.x + threadIdx.x;
    if (e < Ee) {
        int is64 = g_is64;
        unsigned s = load_ei(ei, (size_t)e, is64);
        unsigned d = load_ei(ei, (size_t)Ee + e, is64);
        if (s < Nn && d < Nn) {
            int pos = g_offs[d] + atomicAdd(&g_cnt[d], 1);
            if (pos >= 0 && pos < Ee) g_csrc[pos] = (int)s;
        }
    }
}

// ---------------- fused gather + HMMA layer (TILE 128m x 128n) ----------------
__global__ __launch_bounds__(256, 1) void k_fused(
    const float* __restrict__ gsrc,    // fp32 gather source (stride STR) or null
    const __nv_bfloat16* __restrict__ A0h, const __nv_bfloat16* __restrict__ A0l, // op0 (no-gather)
    const __nv_bfloat16* __restrict__ A1h, const __nv_bfloat16* __restrict__ A1l, // op1 self
    int w0, int w1,
    const float* __restrict__ b0, const float* __restrict__ b1,
    const float* __restrict__ r1wl, const float* __restrict__ r1wr,
    const float* __restrict__ fself,   // fp32 with card col (rank-1 self), or null
    int numOps, int do_relu, int layer0,
    float* __restrict__ fout, int ostride, int ocols,
    __nv_bfloat16* __restrict__ bh_out, __nv_bfloat16* __restrict__ bl_out)
{
    extern __shared__ __align__(16) char smem[];
    uint32_t sb = smem_u32(smem);
    float* auxb = (float*)(smem + S_AUX);
    float* auxl = auxb + 128;
    float* auxr = auxl + 128;
    float* meanbuf = auxr + 128;

    int tid = threadIdx.x;
    int wid = tid >> 5;
    int lane = tid & 31;
    int wr0 = wid * 16;
    int n0 = blockIdx.x * TILE_M;

    if (tid < 128) {
        int cg = tid;
        float bs = (cg < ocols) ? b0[cg] : 0.f;
        if (b1 && cg < ocols) bs += b1[cg];
        auxb[tid] = bs;
        auxl[tid] = r1wl ? r1wl[(size_t)cg * K1] : 0.f;
        auxr[tid] = r1wr ? r1wr[(size_t)cg * K1] : 0.f;
    }

    float acc[16][4];
#pragma unroll
    for (int i = 0; i < 16; i++)
#pragma unroll
        for (int j = 0; j < 4; j++) acc[i][j] = 0.f;

    int q = lane >> 3, r8 = lane & 7;
    uint32_t qrow = (uint32_t)((q & 1) * 8 + r8);
    uint32_t qkb = (uint32_t)((q >> 1) * 16);
    uint32_t a_off = (wr0 + qrow) * RS + qkb;

    for (int op = 0; op < numOps; ++op) {
        if (op) __syncthreads();   // protect smem reuse

        // ---- stage W (async) ----
        {
            const __nv_bfloat16* Wh = g_Whi[op ? w1 : w0];
            const __nv_bfloat16* Wl = g_Wlo[op ? w1 : w0];
            int r = tid >> 1, half = tid & 1;
            const char* srch = (const char*)(Wh + (size_t)r * HD + half * 64);
            const char* srcl = (const char*)(Wl + (size_t)r * HD + half * 64);
            uint32_t dh = sb + S_WHI + r * RS + half * 128;
            uint32_t dl = sb + S_WLO + r * RS + half * 128;
#pragma unroll
            for (int qq = 0; qq < 8; ++qq) {
                CPA(dh + qq * 16, srch + qq * 16);
                CPA(dl + qq * 16, srcl + qq * 16);
            }
        }

        // ---- stage A ----
        if (op == 0 && gsrc) {
            // fused mean-gather straight into smem A tile
            for (int i = 0; i < 16; ++i) {
                int row = wr0 + i;
                int n = n0 + row;
                float4 a4 = make_float4(0.f, 0.f, 0.f, 0.f);
                float accC = 0.f;
                float di = 0.f;
                if (n < Nn) {
                    int st = g_offs[n];
                    int dg = g_degc[n];
                    if (st < 0) st = 0;
                    if (st + dg > Ee) dg = Ee - st;
                    int sNext = (dg > 0) ? g_csrc[st] : 0;
                    for (int e = 0; e < dg; ++e) {
                        int s = sNext;
                        if (e + 1 < dg) sNext = g_csrc[st + e + 1];
                        const float* row_p = gsrc + (size_t)s * STR;
                        float4 v = *(const float4*)(row_p + lane * 4);
                        a4.x += v.x; a4.y += v.y; a4.z += v.z; a4.w += v.w;
                        if (layer0 && lane == 0) accC += row_p[128];
                    }
                    di = (dg > 0) ? 1.f / (float)dg : 0.f;
                }
                a4.x *= di; a4.y *= di; a4.z *= di; a4.w *= di;
                uint2 hv, lv;
                split2(a4.x, a4.y, hv.x, lv.x);
                split2(a4.z, a4.w, hv.y, lv.y);
                *(uint2*)(smem + S_AHI + row * RS + lane * 8) = hv;
                *(uint2*)(smem + S_ALO + row * RS + lane * 8) = lv;
                if (lane == 0) meanbuf[row] = accC * di;
            }
        } else {
            const __nv_bfloat16* Ah = op ? A1h : A0h;
            const __nv_bfloat16* Al = op ? A1l : A0l;
            int r = tid >> 1, half = tid & 1;
            int m = n0 + r;
            uint32_t dh = sb + S_AHI + r * RS + half * 128;
            uint32_t dl = sb + S_ALO + r * RS + half * 128;
            if (m < Nn) {
                const char* srch = (const char*)(Ah + (size_t)m * HD + half * 64);
                const char* srcl = (const char*)(Al + (size_t)m * HD + half * 64);
#pragma unroll
                for (int qq = 0; qq < 8; ++qq) {
                    CPA(dh + qq * 16, srch + qq * 16);
                    CPA(dl + qq * 16, srcl + qq * 16);
                }
            } else {
                uint4 z = make_uint4(0, 0, 0, 0);
#pragma unroll
                for (int qq = 0; qq < 8; ++qq) {
                    *(uint4*)(smem + S_AHI + r * RS + half * 128 + qq * 16) = z;
                    *(uint4*)(smem + S_ALO + r * RS + half * 128 + qq * 16) = z;
                }
            }
        }
        CPA_COMMIT();
        CPA_WAIT();
        __syncthreads();

        // ---- MMA: 8 k-steps x 8 col-tiles, 3 split passes ----
#pragma unroll
        for (int ks = 0; ks < 8; ++ks) {
            uint32_t kb = ks * 32;
            u32 ah[4], al[4];
            LDM4(ah, sb + S_AHI + a_off + kb);
            LDM4(al, sb + S_ALO + a_off + kb);
#pragma unroll
            for (int p = 0; p < 8; ++p) {
                uint32_t boff = (p * 16 + qrow) * RS + qkb + kb;
                u32 bh[4], bl[4];
                LDM4(bh, sb + S_WHI + boff);
                LDM4(bl, sb + S_WLO + boff);
                MMA(acc[2 * p],     ah, bh[0], bh[2]);
                MMA(acc[2 * p],     ah, bl[0], bl[2]);
                MMA(acc[2 * p],     al, bh[0], bh[2]);
                MMA(acc[2 * p + 1], ah, bh[1], bh[3]);
                MMA(acc[2 * p + 1], ah, bl[1], bl[3]);
                MMA(acc[2 * p + 1], al, bh[1], bh[3]);
            }
        }
    }

    // ---- epilogue ----
    int l4 = lane >> 2, c2 = (lane & 3) * 2;
    int rA = n0 + wr0 + l4;
    int rB = rA + 8;
    float mcA = 0.f, scA = 0.f, mcB = 0.f, scB = 0.f;
    if (r1wl) {
        mcA = meanbuf[wr0 + l4];
        mcB = meanbuf[wr0 + l4 + 8];
        if (rA < Nn) scA = fself[(size_t)rA * STR + 128];
        if (rB < Nn) scB = fself[(size_t)rB * STR + 128];
    }
#pragma unroll
    for (int nt = 0; nt < 16; ++nt) {
        int c = nt * 8 + c2;
        float f0 = acc[nt][0] + auxb[c]     + mcA * auxl[c]     + scA * auxr[c];
        float f1 = acc[nt][1] + auxb[c + 1] + mcA * auxl[c + 1] + scA * auxr[c + 1];
        float f2 = acc[nt][2] + auxb[c]     + mcB * auxl[c]     + scB * auxr[c];
        float f3 = acc[nt][3] + auxb[c + 1] + mcB * auxl[c + 1] + scB * auxr[c + 1];
        if (do_relu) {
            f0 = fmaxf(f0, 0.f); f1 = fmaxf(f1, 0.f);
            f2 = fmaxf(f2, 0.f); f3 = fmaxf(f3, 0.f);
        }
        if (fout) {
            if (ocols == HD) {
                if (rA < Nn) *(float2*)(fout + (size_t)rA * ostride + c) = make_float2(f0, f1);
                if (rB < Nn) *(float2*)(fout + (size_t)rB * ostride + c) = make_float2(f2, f3);
            } else {
                if (rA < Nn) {
                    if (c < ocols)     fout[(size_t)rA * ostride + c]     = f0;
                    if (c + 1 < ocols) fout[(size_t)rA * ostride + c + 1] = f1;
                }
                if (rB < Nn) {
                    if (c < ocols)     fout[(size_t)rB * ostride + c]     = f2;
                    if (c + 1 < ocols) fout[(size_t)rB * ostride + c + 1] = f3;
                }
            }
        }
        if (bh_out) {
            u32 hw, lw;
            if (rA < Nn) {
                split2(f0, f1, hw, lw);
                *(u32*)(bh_out + (size_t)rA * HD + c) = hw;
                *(u32*)(bl_out + (size_t)rA * HD + c) = lw;
            }
            if (rB < Nn) {
                split2(f2, f3, hw, lw);
                *(u32*)(bh_out + (size_t)rB * HD + c) = hw;
                *(u32*)(bl_out + (size_t)rB * HD + c) = lw;
            }
        }
    }
}

// ---------------- launch ----------------
extern "C" void kernel_launch(void* const* d_in, const int* in_sizes, int n_in,
                              void* d_out, int out_size) {
    int ix = 0, iWl1 = 1, ibl1 = 2, iWr1 = 3, ibr1 = 4, iWl2 = 5, ibl2 = 6,
        iWr2 = 7, ibr2 = 8, iWo = 9, ibo = 10, iei = 11, icards = 12;
    if (n_in == 13) {
        int w1a[2] = {-1, -1}; int n_w1 = 0;
        int w2a[2] = {-1, -1}; int n_w2 = 0;
        int ba[4] = {-1, -1, -1, -1}; int n_b = 0;
        int f_x = -1, f_Wo = -1, f_bo = -1, f_ei = -1, f_cards = -1;
        for (int i = 0; i < n_in; i++) {
            switch (in_sizes[i]) {
                case (int)((size_t)Nn * FIN): f_x = i; break;
                case HD * K1: if (n_w1 < 2) w1a[n_w1++] = i; break;
                case HD * HD: if (n_w2 < 2) w2a[n_w2++] = i; break;
                case HD:      if (n_b < 4)  ba[n_b++]  = i; break;
                case NCARDS * HD: f_Wo = i; break;
                case NCARDS:      f_bo = i; break;
                case 2 * Ee:      f_ei = i; break;
                case Nn:          f_cards = i; break;
                default: break;
            }
        }
        if (f_x >= 0 && n_w1 == 2 && n_w2 == 2 && n_b == 4 && f_Wo >= 0 &&
            f_bo >= 0 && f_ei >= 0 && f_cards >= 0) {
            ix = f_x; iWl1 = w1a[0]; iWr1 = w1a[1]; iWl2 = w2a[0]; iWr2 = w2a[1];
            ibl1 = ba[0]; ibr1 = ba[1]; ibl2 = ba[2]; ibr2 = ba[3];
            iWo = f_Wo; ibo = f_bo; iei = f_ei; icards = f_cards;
        }
    }

    const float* x   = (const float*)d_in[ix];
    const float* Wl1 = (const float*)d_in[iWl1];
    const float* bl1 = (const float*)d_in[ibl1];
    const float* Wr1 = (const float*)d_in[iWr1];
    const float* br1 = (const float*)d_in[ibr1];
    const float* Wl2 = (const float*)d_in[iWl2];
    const float* bl2 = (const float*)d_in[ibl2];
    const float* Wr2 = (const float*)d_in[iWr2];
    const float* br2 = (const float*)d_in[ibr2];
    const float* Wo  = (const float*)d_in[iWo];
    const float* bo  = (const float*)d_in[ibo];
    const int* ei    = (const int*)d_in[iei];
    const int* cards = (const int*)d_in[icards];
    float* out = (float*)d_out;

    cudaFuncSetAttribute(k_fused, cudaFuncAttributeMaxDynamicSharedMemorySize, SMEM_DYN);

    float *p_h0, *p_h1;
    __nv_bfloat16 *p_b0h, *p_b0l, *p_b1h, *p_b1l, *p_b2h, *p_b2l;
    cudaGetSymbolAddress((void**)&p_h0, g_h0);
    cudaGetSymbolAddress((void**)&p_h1, g_h1);
    cudaGetSymbolAddress((void**)&p_b0h, g_b0h);
    cudaGetSymbolAddress((void**)&p_b0l, g_b0l);
    cudaGetSymbolAddress((void**)&p_b1h, g_b1h);
    cudaGetSymbolAddress((void**)&p_b1l, g_b1l);
    cudaGetSymbolAddress((void**)&p_b2h, g_b2h);
    cudaGetSymbolAddress((void**)&p_b2l, g_b2l);

    k_init<<<(Nn + 255) / 256, 256>>>(ei);
    k_prep_w<<<(5 * HD * HD + 255) / 256, 256>>>(Wl1, Wr1, Wl2, Wr2, Wo);
    k_concat<<<(Nn * 32 + 255) / 256, 256>>>(x, cards);

    k_deghist<<<(Ee + 255) / 256, 256>>>(ei);
    k_scanA<<<(Nn + 1023) / 1024, 1024>>>();
    k_place<<<(Ee + 255) / 256, 256>>>(ei);

    // layer 1: gather from h0 + self(b0) -> h1 fp32 + split b1
    k_fused<<<NTILES, 256, SMEM_DYN>>>(p_h0, nullptr, nullptr, p_b0h, p_b0l,
                                       0, 1, bl1, br1, Wl1 + 128, Wr1 + 128, p_h0,
                                       2, 1, 1, p_h1, STR, HD, p_b1h, p_b1l);

    // layer 2: gather from h1 + self(b1) -> split b2
    k_fused<<<NTILES, 256, SMEM_DYN>>>(p_h1, nullptr, nullptr, p_b1h, p_b1l,
                                       2, 3, bl2, br2, nullptr, nullptr, nullptr,
                                       2, 1, 0, nullptr, 0, HD, p_b2h, p_b2l);

    // output head: b2 @ Wo^T + bo
    k_fused<<<NTILES, 256, SMEM_DYN>>>(nullptr, p_b2h, p_b2l, nullptr, nullptr,
                                       4, 4, bo, nullptr, nullptr, nullptr, nullptr,
                                       1, 0, 0, out, NCARDS, NCARDS, nullptr, nullptr);
}

// round 9
// speedup vs baseline: 1.5196x; 1.5196x over previous
#include <cuda_runtime.h>
#include <cuda_bf16.h>
#include <cstdint>

#define Nn 100000
#define Ee 1600000
#define FIN 128
#define K1 129
#define HD 128
#define NCARDS 110
#define TILE_M 128
#define NTILES ((Nn + TILE_M - 1) / TILE_M)   // 782

typedef unsigned int u32;

// ---------------- device scratch ----------------
// split-bf16 feature copies, row-major [n][128]
__device__ __nv_bfloat16 g_b0h[(size_t)Nn * HD], g_b0l[(size_t)Nn * HD];
__device__ __nv_bfloat16 g_b1h[(size_t)Nn * HD], g_b1l[(size_t)Nn * HD];
__device__ __nv_bfloat16 g_b2h[(size_t)Nn * HD], g_b2l[(size_t)Nn * HD];
__device__ __nv_bfloat16 g_bsh[(size_t)Nn * HD], g_bsl[(size_t)Nn * HD]; // mean-agg
__device__ float g_cardf[Nn];              // self card (fp32)
__device__ float g_meanC[Nn];              // mean card over neighbors
// bf16 split weights: 0=Wl1,1=Wr1,2=Wl2,3=Wr2,4=Wo (padded [128,128], row-major [n][k])
__device__ __nv_bfloat16 g_Whi[5][HD * HD];
__device__ __nv_bfloat16 g_Wlo[5][HD * HD];
__device__ int g_degc[Nn];
__device__ int g_cnt[Nn];
__device__ int g_offs[Nn];
__device__ int g_csrc[Ee];
__device__ int g_tot;
__device__ int g_is64;

// ---------------- helpers ----------------
__device__ __forceinline__ unsigned load_ei(const int* p, size_t i, int is64) {
    if (is64) return (unsigned)((const long long*)p)[i];
    return (unsigned)p[i];
}
__device__ __forceinline__ uint32_t smem_u32(const void* p) {
    uint32_t a;
    asm("{ .reg .u64 t; cvta.to.shared.u64 t, %1; cvt.u32.u64 %0, t; }" : "=r"(a) : "l"(p));
    return a;
}
__device__ __forceinline__ u32 cvt2(float a, float b) {
    __nv_bfloat162 t = __floats2bfloat162_rn(a, b);
    return *(u32*)&t;
}
__device__ __forceinline__ void split2(float f0, float f1, u32& hw, u32& lw) {
    __nv_bfloat16 h0 = __float2bfloat16_rn(f0);
    __nv_bfloat16 h1 = __float2bfloat16_rn(f1);
    hw = ((u32)*(unsigned short*)&h1 << 16) | *(unsigned short*)&h0;
    lw = cvt2(f0 - __bfloat162float(h0), f1 - __bfloat162float(h1));
}
// accumulate 4 floats from split bf16 uint2 pair
__device__ __forceinline__ void acc4(float4& a, uint2 h, uint2 l) {
    float2 h0 = __bfloat1622float2(*(__nv_bfloat162*)&h.x);
    float2 h1 = __bfloat1622float2(*(__nv_bfloat162*)&h.y);
    float2 l0 = __bfloat1622float2(*(__nv_bfloat162*)&l.x);
    float2 l1 = __bfloat1622float2(*(__nv_bfloat162*)&l.y);
    a.x += h0.x + l0.x; a.y += h0.y + l0.y;
    a.z += h1.x + l1.x; a.w += h1.y + l1.y;
}

#define LDM4(r, addr) \
    asm volatile("ldmatrix.sync.aligned.m8n8.x4.shared.b16 {%0,%1,%2,%3}, [%4];" \
                 : "=r"((r)[0]), "=r"((r)[1]), "=r"((r)[2]), "=r"((r)[3]) : "r"(addr))

#define MMA(c, a, bb0, bb1) \
    asm volatile("mma.sync.aligned.m16n8k16.row.col.f32.bf16.bf16.f32 " \
                 "{%0,%1,%2,%3},{%4,%5,%6,%7},{%8,%9},{%0,%1,%2,%3};" \
                 : "+f"((c)[0]), "+f"((c)[1]), "+f"((c)[2]), "+f"((c)[3]) \
                 : "r"((a)[0]), "r"((a)[1]), "r"((a)[2]), "r"((a)[3]), "r"(bb0), "r"(bb1))

#define CPA(dst, src) \
    asm volatile("cp.async.cg.shared.global [%0], [%1], 16;" :: "r"(dst), "l"(src))
#define CPA_COMMIT() asm volatile("cp.async.commit_group;" ::: "memory")
#define CPA_WAIT()   asm volatile("cp.async.wait_group 0;" ::: "memory")

// smem; row stride 272B = 17*16 -> conflict-free ldmatrix
#define RS 272
#define S_AHI 0
#define S_ALO 34816
#define S_WHI 69632
#define S_WLO 87040
#define S_AUX 104448            // auxb[64], auxl[64], auxr[64] floats
#define SMEM_DYN (104448 + 3 * 64 * 4)

// ---------------- setup (+dtype detect) ----------------
__global__ void k_init(const int* __restrict__ ei32) {
    int i = blockIdx.x * blockDim.x + threadIdx.x;
    if (i < Nn) { g_degc[i] = 0; g_cnt[i] = 0; }
    if (i == 0) {
        g_tot = 0;
        int all_zero = 1;
        for (int w = 1; w < 64; w += 2)
            if (ei32[w] != 0) { all_zero = 0; break; }
        g_is64 = all_zero;
    }
}

__global__ void k_prep_w(const float* __restrict__ Wl1, const float* __restrict__ Wr1,
                         const float* __restrict__ Wl2, const float* __restrict__ Wr2,
                         const float* __restrict__ Wo) {
    int i = blockIdx.x * blockDim.x + threadIdx.x;
    if (i >= 5 * HD * HD) return;
    int op = i / (HD * HD);
    int r = i % (HD * HD);
    int n = r / HD, k = r % HD;
    float v = 0.f;
    if (op == 0) v = Wl1[n * K1 + k];
    else if (op == 1) v = Wr1[n * K1 + k];
    else if (op == 2) v = Wl2[n * HD + k];
    else if (op == 3) v = Wr2[n * HD + k];
    else if (n < NCARDS) v = Wo[n * HD + k];
    __nv_bfloat16 h = __float2bfloat16_rn(v);
    g_Whi[op][r] = h;
    g_Wlo[op][r] = __float2bfloat16_rn(v - __bfloat162float(h));
}

__global__ void k_concat(const float* __restrict__ x, const int* __restrict__ cards) {
    int i = blockIdx.x * blockDim.x + threadIdx.x;
    if (i >= Nn * 32) return;
    int n = i >> 5, c = (i & 31) * 4;
    float4 v = *(const float4*)(x + (size_t)n * FIN + c);
    uint2 hv, lv;
    split2(v.x, v.y, hv.x, lv.x);
    split2(v.z, v.w, hv.y, lv.y);
    *(uint2*)(g_b0h + (size_t)n * HD + c) = hv;
    *(uint2*)(g_b0l + (size_t)n * HD + c) = lv;
    if ((i & 31) == 0) g_cardf[n] = (float)cards[n];
}

// ---------------- CSR build ----------------
__global__ void k_deghist(const int* __restrict__ ei) {
    int e = blockIdx.x * blockDim.x + threadIdx.x;
    if (e < Ee) {
        unsigned d = load_ei(ei, (size_t)Ee + e, g_is64);
        if (d < Nn) atomicAdd(&g_degc[d], 1);
    }
}

__global__ void k_scanA() {
    __shared__ int sh[1024];
    __shared__ int base;
    int t = threadIdx.x;
    int n = blockIdx.x * 1024 + t;
    int v = (n < Nn) ? g_degc[n] : 0;
    sh[t] = v;
    __syncthreads();
    for (int off = 1; off < 1024; off <<= 1) {
        int add = (t >= off) ? sh[t - off] : 0;
        __syncthreads();
        sh[t] += add;
        __syncthreads();
    }
    if (t == 1023) base = atomicAdd(&g_tot, sh[1023]);
    __syncthreads();
    if (n < Nn) g_offs[n] = base + sh[t] - v;
}

__global__ void k_place(const int* __restrict__ ei) {
    int e = blockIdx.x * blockDim.x + threadIdx.x;
    if (e < Ee) {
        int is64 = g_is64;
        unsigned s = load_ei(ei, (size_t)e, is64);
        unsigned d = load_ei(ei, (size_t)Ee + e, is64);
        if (s < Nn && d < Nn) {
            int pos = g_offs[d] + atomicAdd(&g_cnt[d], 1);
            if (pos >= 0 && pos < Ee) g_csrc[pos] = (int)s;
        }
    }
}

// ---------------- gather mean-aggregation (split-bf16 src, MLP=4) ----------------
__global__ void k_gather(const __nv_bfloat16* __restrict__ sh_,
                         const __nv_bfloat16* __restrict__ sl_, int layer0) {
    int gw = (blockIdx.x * blockDim.x + threadIdx.x) >> 5;
    int lane = threadIdx.x & 31;
    int nw = (gridDim.x * blockDim.x) >> 5;
    for (int n = gw; n < Nn; n += nw) {
        int st = g_offs[n];
        int dg = g_degc[n];
        if (st < 0) st = 0;
        if (st + dg > Ee) dg = Ee - st;
        float4 acc = make_float4(0.f, 0.f, 0.f, 0.f);
        float accC = 0.f;
        int i = 0;
        for (; i + 4 <= dg; i += 4) {
            int s0 = g_csrc[st + i];
            int s1 = g_csrc[st + i + 1];
            int s2 = g_csrc[st + i + 2];
            int s3 = g_csrc[st + i + 3];
            uint2 h0 = *(const uint2*)(sh_ + (size_t)s0 * HD + lane * 4);
            uint2 l0 = *(const uint2*)(sl_ + (size_t)s0 * HD + lane * 4);
            uint2 h1 = *(const uint2*)(sh_ + (size_t)s1 * HD + lane * 4);
            uint2 l1 = *(const uint2*)(sl_ + (size_t)s1 * HD + lane * 4);
            uint2 h2 = *(const uint2*)(sh_ + (size_t)s2 * HD + lane * 4);
            uint2 l2 = *(const uint2*)(sl_ + (size_t)s2 * HD + lane * 4);
            uint2 h3 = *(const uint2*)(sh_ + (size_t)s3 * HD + lane * 4);
            uint2 l3 = *(const uint2*)(sl_ + (size_t)s3 * HD + lane * 4);
            acc4(acc, h0, l0); acc4(acc, h1, l1);
            acc4(acc, h2, l2); acc4(acc, h3, l3);
            if (layer0 && lane == 0)
                accC += g_cardf[s0] + g_cardf[s1] + g_cardf[s2] + g_cardf[s3];
        }
        for (; i < dg; ++i) {
            int s = g_csrc[st + i];
            uint2 h = *(const uint2*)(sh_ + (size_t)s * HD + lane * 4);
            uint2 l = *(const uint2*)(sl_ + (size_t)s * HD + lane * 4);
            acc4(acc, h, l);
            if (layer0 && lane == 0) accC += g_cardf[s];
        }
        float di = (dg > 0) ? 1.f / (float)dg : 0.f;
        acc.x *= di; acc.y *= di; acc.z *= di; acc.w *= di;
        uint2 hv, lv;
        split2(acc.x, acc.y, hv.x, lv.x);
        split2(acc.z, acc.w, hv.y, lv.y);
        *(uint2*)(g_bsh + (size_t)n * HD + lane * 4) = hv;
        *(uint2*)(g_bsl + (size_t)n * HD + lane * 4) = lv;
        if (layer0 && lane == 0) g_meanC[n] = accC * di;
    }
}

// ---------------- HMMA fused layer (TILE 128m x 64n) ----------------
__global__ __launch_bounds__(256, 2) void k_mma(
    const __nv_bfloat16* __restrict__ A0h, const __nv_bfloat16* __restrict__ A0l,
    const __nv_bfloat16* __restrict__ A1h, const __nv_bfloat16* __restrict__ A1l,
    int w0, int w1,
    const float* __restrict__ b0, const float* __restrict__ b1,
    const float* __restrict__ r1wl, const float* __restrict__ r1wr,
    int numOps, int do_relu,
    float* __restrict__ fout, int ostride, int ocols,
    __nv_bfloat16* __restrict__ bh_out, __nv_bfloat16* __restrict__ bl_out)
{
    extern __shared__ __align__(16) char smem[];
    uint32_t sb = smem_u32(smem);
    float* auxb = (float*)(smem + S_AUX);
    float* auxl = auxb + 64;
    float* auxr = auxl + 64;

    int tid = threadIdx.x;
    int wid = tid >> 5;
    int lane = tid & 31;
    int wr0 = wid * 16;
    int n0 = blockIdx.x * TILE_M;
    int c_base = blockIdx.y * 64;

    if (tid < 64) {
        int cg = c_base + tid;
        float bs = (cg < ocols) ? b0[cg] : 0.f;
        if (b1 && cg < ocols) bs += b1[cg];
        auxb[tid] = bs;
        auxl[tid] = r1wl ? r1wl[(size_t)cg * K1] : 0.f;
        auxr[tid] = r1wr ? r1wr[(size_t)cg * K1] : 0.f;
    }

    float acc[8][4];
#pragma unroll
    for (int i = 0; i < 8; i++)
#pragma unroll
        for (int j = 0; j < 4; j++) acc[i][j] = 0.f;

    int q = lane >> 3, r8 = lane & 7;
    uint32_t qrow = (uint32_t)((q & 1) * 8 + r8);
    uint32_t qkb = (uint32_t)((q >> 1) * 16);
    uint32_t a_off = (wr0 + qrow) * RS + qkb;

    for (int op = 0; op < numOps; ++op) {
        if (op) __syncthreads();
        const __nv_bfloat16* Ah = op ? A1h : A0h;
        const __nv_bfloat16* Al = op ? A1l : A0l;
        const __nv_bfloat16* Wh = g_Whi[op ? w1 : w0];
        const __nv_bfloat16* Wl = g_Wlo[op ? w1 : w0];

        // stage A (16B cp.async)
        {
            int r = tid >> 1, half = tid & 1;
            int m = n0 + r;
            uint32_t dh = sb + S_AHI + r * RS + half * 128;
            uint32_t dl = sb + S_ALO + r * RS + half * 128;
            if (m < Nn) {
                const char* srch = (const char*)(Ah + (size_t)m * HD + half * 64);
                const char* srcl = (const char*)(Al + (size_t)m * HD + half * 64);
#pragma unroll
                for (int qq = 0; qq < 8; ++qq) {
                    CPA(dh + qq * 16, srch + qq * 16);
                    CPA(dl + qq * 16, srcl + qq * 16);
                }
            } else {
                uint4 z = make_uint4(0, 0, 0, 0);
#pragma unroll
                for (int qq = 0; qq < 8; ++qq) {
                    *(uint4*)(smem + S_AHI + r * RS + half * 128 + qq * 16) = z;
                    *(uint4*)(smem + S_ALO + r * RS + half * 128 + qq * 16) = z;
                }
            }
        }
        // stage W (64 rows of this col-half)
        {
            int r = tid >> 2, qtr = tid & 3;
            int nrow = c_base + r;
            const char* srch = (const char*)(Wh + (size_t)nrow * HD + qtr * 32);
            const char* srcl = (const char*)(Wl + (size_t)nrow * HD + qtr * 32);
            uint32_t dh = sb + S_WHI + r * RS + qtr * 64;
            uint32_t dl = sb + S_WLO + r * RS + qtr * 64;
#pragma unroll
            for (int qq = 0; qq < 4; ++qq) {
                CPA(dh + qq * 16, srch + qq * 16);
                CPA(dl + qq * 16, srcl + qq * 16);
            }
        }
        CPA_COMMIT();
        CPA_WAIT();
        __syncthreads();

#pragma unroll
        for (int ks = 0; ks < 8; ++ks) {
            uint32_t kb = ks * 32;
            u32 ah[4], al[4];
            LDM4(ah, sb + S_AHI + a_off + kb);
            LDM4(al, sb + S_ALO + a_off + kb);
#pragma unroll
            for (int p = 0; p < 4; ++p) {
                uint32_t boff = (p * 16 + qrow) * RS + qkb + kb;
                u32 bh[4], bl[4];
                LDM4(bh, sb + S_WHI + boff);
                LDM4(bl, sb + S_WLO + boff);
                MMA(acc[2 * p],     ah, bh[0], bh[2]);
                MMA(acc[2 * p],     ah, bl[0], bl[2]);
                MMA(acc[2 * p],     al, bh[0], bh[2]);
                MMA(acc[2 * p + 1], ah, bh[1], bh[3]);
                MMA(acc[2 * p + 1], ah, bl[1], bl[3]);
                MMA(acc[2 * p + 1], al, bh[1], bh[3]);
            }
        }
    }

    // epilogue
    int l4 = lane >> 2, c2 = (lane & 3) * 2;
    int rA = n0 + wr0 + l4;
    int rB = rA + 8;
    float mcA = 0.f, scA = 0.f, mcB = 0.f, scB = 0.f;
    if (r1wl) {
        if (rA < Nn) { mcA = g_meanC[rA]; scA = g_cardf[rA]; }
        if (rB < Nn) { mcB = g_meanC[rB]; scB = g_cardf[rB]; }
    }
#pragma unroll
    for (int nt = 0; nt < 8; ++nt) {
        int c = nt * 8 + c2;
        int gc = c_base + c;
        float f0 = acc[nt][0] + auxb[c]     + mcA * auxl[c]     + scA * auxr[c];
        float f1 = acc[nt][1] + auxb[c + 1] + mcA * auxl[c + 1] + scA * auxr[c + 1];
        float f2 = acc[nt][2] + auxb[c]     + mcB * auxl[c]     + scB * auxr[c];
        float f3 = acc[nt][3] + auxb[c + 1] + mcB * auxl[c + 1] + scB * auxr[c + 1];
        if (do_relu) {
            f0 = fmaxf(f0, 0.f); f1 = fmaxf(f1, 0.f);
            f2 = fmaxf(f2, 0.f); f3 = fmaxf(f3, 0.f);
        }
        if (fout) {
            if (rA < Nn) {
                if (gc < ocols)     fout[(size_t)rA * ostride + gc]     = f0;
                if (gc + 1 < ocols) fout[(size_t)rA * ostride + gc + 1] = f1;
            }
            if (rB < Nn) {
                if (gc < ocols)     fout[(size_t)rB * ostride + gc]     = f2;
                if (gc + 1 < ocols) fout[(size_t)rB * ostride + gc + 1] = f3;
            }
        }
        if (bh_out) {
            u32 hw, lw;
            if (rA < Nn) {
                split2(f0, f1, hw, lw);
                *(u32*)(bh_out + (size_t)rA * HD + gc) = hw;
                *(u32*)(bl_out + (size_t)rA * HD + gc) = lw;
            }
            if (rB < Nn) {
                split2(f2, f3, hw, lw);
                *(u32*)(bh_out + (size_t)rB * HD + gc) = hw;
                *(u32*)(bl_out + (size_t)rB * HD + gc) = lw;
            }
        }
    }
}

// ---------------- launch ----------------
extern "C" void kernel_launch(void* const* d_in, const int* in_sizes, int n_in,
                              void* d_out, int out_size) {
    int ix = 0, iWl1 = 1, ibl1 = 2, iWr1 = 3, ibr1 = 4, iWl2 = 5, ibl2 = 6,
        iWr2 = 7, ibr2 = 8, iWo = 9, ibo = 10, iei = 11, icards = 12;
    if (n_in == 13) {
        int w1a[2] = {-1, -1}; int n_w1 = 0;
        int w2a[2] = {-1, -1}; int n_w2 = 0;
        int ba[4] = {-1, -1, -1, -1}; int n_b = 0;
        int f_x = -1, f_Wo = -1, f_bo = -1, f_ei = -1, f_cards = -1;
        for (int i = 0; i < n_in; i++) {
            switch (in_sizes[i]) {
                case (int)((size_t)Nn * FIN): f_x = i; break;
                case HD * K1: if (n_w1 < 2) w1a[n_w1++] = i; break;
                case HD * HD: if (n_w2 < 2) w2a[n_w2++] = i; break;
                case HD:      if (n_b < 4)  ba[n_b++]  = i; break;
                case NCARDS * HD: f_Wo = i; break;
                case NCARDS:      f_bo = i; break;
                case 2 * Ee:      f_ei = i; break;
                case Nn:          f_cards = i; break;
                default: break;
            }
        }
        if (f_x >= 0 && n_w1 == 2 && n_w2 == 2 && n_b == 4 && f_Wo >= 0 &&
            f_bo >= 0 && f_ei >= 0 && f_cards >= 0) {
            ix = f_x; iWl1 = w1a[0]; iWr1 = w1a[1]; iWl2 = w2a[0]; iWr2 = w2a[1];
            ibl1 = ba[0]; ibr1 = ba[1]; ibl2 = ba[2]; ibr2 = ba[3];
            iWo = f_Wo; ibo = f_bo; iei = f_ei; icards = f_cards;
        }
    }

    const float* x   = (const float*)d_in[ix];
    const float* Wl1 = (const float*)d_in[iWl1];
    const float* bl1 = (const float*)d_in[ibl1];
    const float* Wr1 = (const float*)d_in[iWr1];
    const float* br1 = (const float*)d_in[ibr1];
    const float* Wl2 = (const float*)d_in[iWl2];
    const float* bl2 = (const float*)d_in[ibl2];
    const float* Wr2 = (const float*)d_in[iWr2];
    const float* br2 = (const float*)d_in[ibr2];
    const float* Wo  = (const float*)d_in[iWo];
    const float* bo  = (const float*)d_in[ibo];
    const int* ei    = (const int*)d_in[iei];
    const int* cards = (const int*)d_in[icards];
    float* out = (float*)d_out;

    cudaFuncSetAttribute(k_mma, cudaFuncAttributeMaxDynamicSharedMemorySize, SMEM_DYN);

    __nv_bfloat16 *p_b0h, *p_b0l, *p_b1h, *p_b1l, *p_b2h, *p_b2l, *p_bsh, *p_bsl;
    cudaGetSymbolAddress((void**)&p_b0h, g_b0h);
    cudaGetSymbolAddress((void**)&p_b0l, g_b0l);
    cudaGetSymbolAddress((void**)&p_b1h, g_b1h);
    cudaGetSymbolAddress((void**)&p_b1l, g_b1l);
    cudaGetSymbolAddress((void**)&p_b2h, g_b2h);
    cudaGetSymbolAddress((void**)&p_b2l, g_b2l);
    cudaGetSymbolAddress((void**)&p_bsh, g_bsh);
    cudaGetSymbolAddress((void**)&p_bsl, g_bsl);

    dim3 mg(NTILES, 2);

    k_init<<<(Nn + 255) / 256, 256>>>(ei);
    k_prep_w<<<(5 * HD * HD + 255) / 256, 256>>>(Wl1, Wr1, Wl2, Wr2, Wo);
    k_concat<<<(Nn * 32 + 255) / 256, 256>>>(x, cards);

    k_deghist<<<(Ee + 255) / 256, 256>>>(ei);
    k_scanA<<<(Nn + 1023) / 1024, 1024>>>();
    k_place<<<(Ee + 255) / 256, 256>>>(ei);

    // layer 1
    k_gather<<<2048, 256>>>(p_b0h, p_b0l, 1);
    k_mma<<<mg, 256, SMEM_DYN>>>(p_bsh, p_bsl, p_b0h, p_b0l, 0, 1, bl1, br1,
                                 Wl1 + 128, Wr1 + 128, 2, 1,
                                 nullptr, 0, HD, p_b1h, p_b1l);

    // layer 2
    k_gather<<<2048, 256>>>(p_b1h, p_b1l, 0);
    k_mma<<<mg, 256, SMEM_DYN>>>(p_bsh, p_bsl, p_b1h, p_b1l, 2, 3, bl2, br2,
                                 nullptr, nullptr, 2, 1,
                                 nullptr, 0, HD, p_b2h, p_b2l);

    // output head
    k_mma<<<mg, 256, SMEM_DYN>>>(p_b2h, p_b2l, nullptr, nullptr, 4, 4, bo, nullptr,
                                 nullptr, nullptr, 1, 0,
                                 out, NCARDS, NCARDS, nullptr, nullptr);
}